// round 2
// baseline (speedup 1.0000x reference)
#include <cuda_runtime.h>

#define EMB     300
#define EMB4    75          // EMB / 4
#define TASKS   12
#define POOL_THREADS 320    // 300 active loaders + round to warp multiple

// Device-global scratch (no allocations allowed in kernel_launch).
__device__ int g_starts[16385 * 2];  // sized generously; starts[g] used for g in [0,G]

// ---------------------------------------------------------------------------
// Fill g_starts: for sorted batch, starts[g] = lower_bound(batch, g).
// int32 vs int64 detection inlined: interpreted as int32 words, word[N-1] is
//   - int32 buffer: last (max) graph id  -> > 0
//   - int64 buffer: HIGH word of elem (N-1)/2 -> 0  (ids in [0, 2^31))
// ---------------------------------------------------------------------------
__global__ void starts_kernel(const void* __restrict__ batch, int N, int G) {
    int i = blockIdx.x * blockDim.x + threadIdx.x;
    if (i >= N) return;
    const int* b32 = (const int*)batch;
    int is64 = (b32[N - 1] == 0);

    long long cur, prev;
    if (is64) {
        const long long* b64 = (const long long*)batch;
        cur  = b64[i];
        prev = (i > 0) ? b64[i - 1] : -1;
    } else {
        cur  = b32[i];
        prev = (i > 0) ? b32[i - 1] : -1;
    }
    for (long long g = prev + 1; g <= cur; ++g) {
        if (g >= 0 && g <= (long long)G) g_starts[g] = i;
    }
    if (i == N - 1) {
        for (long long g = cur + 1; g <= (long long)G; ++g) g_starts[g] = N;
    }
}

// ---------------------------------------------------------------------------
// One CTA per graph. Threads 0..299: float4 column c = t%75, row-offset
// ro = t/75. Main loop steps 8 rows with two independent float4 accumulators
// (LDG.128, fully coalesced: lanes 0..74 cover one 1200B row). Reduction in
// shared, then fused 300->12 head + mean-scale + bias.
// ---------------------------------------------------------------------------
__global__ __launch_bounds__(POOL_THREADS)
void pool_head_kernel(const float* __restrict__ x,
                      const float* __restrict__ W,
                      const float* __restrict__ b,
                      float* __restrict__ out) {
    int g = blockIdx.x;
    __shared__ float4 sh4[300];   // per-thread partial sums
    __shared__ float4 shF4[EMB4]; // final column sums (aliased as float[300])

    int lo = g_starts[g];
    int hi = g_starts[g + 1];

    int t = threadIdx.x;
    if (t < 300) {
        int c  = t % EMB4;   // float4 column 0..74
        int ro = t / EMB4;   // row offset 0..3
        const float4* p0 = (const float4*)(x + (size_t)(lo + ro) * EMB) + c;

        float4 a0 = make_float4(0.f, 0.f, 0.f, 0.f);
        float4 a1 = make_float4(0.f, 0.f, 0.f, 0.f);

        int r = lo;
        // main loop: 8 rows per iteration, 2 independent LDG.128 per thread
        for (; r + 8 <= hi; r += 8) {
            float4 v0 = p0[0];
            float4 v1 = p0[4 * EMB4];
            a0.x += v0.x; a0.y += v0.y; a0.z += v0.z; a0.w += v0.w;
            a1.x += v1.x; a1.y += v1.y; a1.z += v1.z; a1.w += v1.w;
            p0 += 8 * EMB4;
        }
        // remainder (0..7 rows): this thread covers rows r+ro and r+ro+4
        if (r + ro < hi) {
            float4 v0 = p0[0];
            a0.x += v0.x; a0.y += v0.y; a0.z += v0.z; a0.w += v0.w;
        }
        if (r + ro + 4 < hi) {
            float4 v1 = p0[4 * EMB4];
            a1.x += v1.x; a1.y += v1.y; a1.z += v1.z; a1.w += v1.w;
        }
        a0.x += a1.x; a0.y += a1.y; a0.z += a1.z; a0.w += a1.w;
        sh4[t] = a0;
    }
    __syncthreads();

    // combine the 4 row-offset groups -> final column sums
    if (t < EMB4) {
        float4 s0 = sh4[t];
        float4 s1 = sh4[t + EMB4];
        float4 s2 = sh4[t + 2 * EMB4];
        float4 s3 = sh4[t + 3 * EMB4];
        float4 f;
        f.x = (s0.x + s1.x) + (s2.x + s3.x);
        f.y = (s0.y + s1.y) + (s2.y + s3.y);
        f.z = (s0.z + s1.z) + (s2.z + s3.z);
        f.w = (s0.w + s1.w) + (s2.w + s3.w);
        shF4[t] = f;
    }
    __syncthreads();

    const float* shF = (const float*)shF4;
    int wid  = t >> 5;
    int lane = t & 31;
    float inv = 1.0f / fmaxf((float)(hi - lo), 1.0f);

    // 10 warps cover 12 tasks (warps 0,1 take a second task).
    for (int task = wid; task < TASKS; task += 10) {
        const float* wrow = W + task * EMB;
        float a = 0.f;
        #pragma unroll
        for (int d = lane; d < EMB; d += 32) {
            a += shF[d] * __ldg(&wrow[d]);
        }
        #pragma unroll
        for (int o = 16; o; o >>= 1) a += __shfl_xor_sync(0xffffffffu, a, o);
        if (lane == 0) {
            out[(size_t)g * TASKS + task] = a * inv + b[task];
        }
    }
}

// ---------------------------------------------------------------------------
// kernel_launch — inputs: x [N,300] f32, batch [N] int32/int64 (sorted),
// W [12,300] f32, b [12] f32, (num_graphs scalar, unused). out: [G,12] f32.
// ---------------------------------------------------------------------------
extern "C" void kernel_launch(void* const* d_in, const int* in_sizes, int n_in,
                              void* d_out, int out_size) {
    const float* x     = (const float*)d_in[0];
    const void*  batch = d_in[1];
    const float* W     = (const float*)d_in[2];
    const float* b     = (const float*)d_in[3];
    float*       out   = (float*)d_out;

    int N = in_sizes[1];        // node count
    int G = out_size / TASKS;   // 16384

    starts_kernel<<<(N + 255) / 256, 256>>>(batch, N, G);
    pool_head_kernel<<<G, POOL_THREADS>>>(x, W, b, out);
}